// round 1
// baseline (speedup 1.0000x reference)
#include <cuda_runtime.h>
#include <math.h>

// ---------------- constants ----------------
#define BB 4
#define HFD 128
#define WFD 128
#define KPRE 2000
#define KOUT 500

// ---------------- scratch (device globals; no allocation allowed) ----------------
__device__ __align__(16) float g_x1[(size_t)4 * 256 * 256 * 64];       // conv1 out
__device__ __align__(16) float g_feat[(size_t)4 * 128 * 128 * 256];    // conv2 out
__device__ __align__(16) float g_segr[(size_t)4 * 128 * 128 * 32];     // reduced seg feats
__device__ __align__(16) float g_scores[4 * 16384];
__device__ __align__(16) float g_reg[4 * 16384 * 2];
__device__ __align__(16) float g_topsc[4 * KPRE];
__device__ __align__(16) float g_locs[4 * KPRE * 2];
__device__ __align__(16) unsigned g_sup[(size_t)4 * KPRE * 64];        // suppression bitmatrix
__device__ int g_sel[4 * KOUT];
__device__ int g_nsel[4];
__device__ int g_tl[4 * KOUT * 2];
__device__ __align__(16) float g_instfull[4 * 128 * 128];

__device__ __forceinline__ float sigmoidf(float z) { return 1.f / (1.f + expf(-z)); }

// ---------------- conv1: 3x3 s2, 3->64, relu. SAME => iy = 2y+ky (pad_lo=0) ----------------
__global__ void conv1_kernel(const float* __restrict__ img, const float* __restrict__ w1,
                             const float* __restrict__ b1) {
    int co = threadIdx.x;                       // 64
    int x  = blockIdx.x * 4 + threadIdx.y;      // 256
    int y  = blockIdx.y;                        // 256
    int b  = blockIdx.z;                        // 4
    float acc = 0.f;
#pragma unroll
    for (int ky = 0; ky < 3; ky++) {
        int iy = 2 * y + ky;
        if (iy >= 512) continue;
#pragma unroll
        for (int kx = 0; kx < 3; kx++) {
            int ix = 2 * x + kx;
            if (ix >= 512) continue;
            const float* ip = img + ((size_t)(b * 512 + iy) * 512 + ix) * 3;
#pragma unroll
            for (int ci = 0; ci < 3; ci++)
                acc += __ldg(ip + ci) * __ldg(w1 + ((ky * 3 + kx) * 3 + ci) * 64 + co);
        }
    }
    acc += __ldg(b1 + co);
    g_x1[((size_t)(b * 256 + y) * 256 + x) * 64 + co] = fmaxf(acc, 0.f);
}

// ---------------- conv2: 3x3 s2, 64->256, relu ----------------
// block = 256 threads = 64 co-quads x 4 output rows; 8 output cols per thread.
__global__ void conv2_kernel(const float* __restrict__ w2, const float* __restrict__ b2) {
    __shared__ float sm[9 * 17 * 64];           // input tile (rows 2y0..2y0+8, cols 2x0..2x0+16)
    int x0 = blockIdx.x * 8, y0 = blockIdx.y * 4, b = blockIdx.z;
    int t = threadIdx.x;
    for (int e = t; e < 9 * 17 * 64; e += 256) {
        int ci = e & 63; int rc = e >> 6; int c = rc % 17; int r = rc / 17;
        int iy = 2 * y0 + r, ix = 2 * x0 + c;
        float v = 0.f;
        if (iy < 256 && ix < 256) v = g_x1[((size_t)(b * 256 + iy) * 256 + ix) * 64 + ci];
        sm[e] = v;
    }
    __syncthreads();
    int co4 = t & 63, ry = t >> 6;
    float a0[8], a1[8], a2[8], a3[8];
#pragma unroll
    for (int p = 0; p < 8; p++) { a0[p] = a1[p] = a2[p] = a3[p] = 0.f; }
#pragma unroll
    for (int ky = 0; ky < 3; ky++) {
        int r = 2 * ry + ky;
#pragma unroll
        for (int kx = 0; kx < 3; kx++) {
            const float* sbase = sm + (r * 17 + kx) * 64;
            const float* wbase = w2 + (size_t)((ky * 3 + kx) * 64) * 256 + co4 * 4;
            for (int ci = 0; ci < 64; ci++) {
                float4 w = *(const float4*)(wbase + (size_t)ci * 256);
#pragma unroll
                for (int p = 0; p < 8; p++) {
                    float v = sbase[(2 * p) * 64 + ci];
                    a0[p] += v * w.x; a1[p] += v * w.y; a2[p] += v * w.z; a3[p] += v * w.w;
                }
            }
        }
    }
    int y = y0 + ry;
    float4 bb = *(const float4*)(b2 + co4 * 4);
#pragma unroll
    for (int p = 0; p < 8; p++) {
        float4 o;
        o.x = fmaxf(a0[p] + bb.x, 0.f); o.y = fmaxf(a1[p] + bb.y, 0.f);
        o.z = fmaxf(a2[p] + bb.z, 0.f); o.w = fmaxf(a3[p] + bb.w, 0.f);
        *(float4*)(g_feat + ((size_t)(b * 128 + y) * 128 + (x0 + p)) * 256 + co4 * 4) = o;
    }
}

// ---------------- detection heads: scores (sigmoid) + reg, both 3x3 s1 SAME (centered) ----------------
__global__ void heads_kernel(const float* __restrict__ wsc, const float* __restrict__ bsc,
                             const float* __restrict__ wrg, const float* __restrict__ brg) {
    int b = blockIdx.y;
    int warp = threadIdx.x >> 5, lane = threadIdx.x & 31;
    int p = blockIdx.x * 8 + warp;
    int y = p >> 7, x = p & 127;
    float as = 0.f, ay = 0.f, ax = 0.f;
    for (int e = lane; e < 2304; e += 32) {
        int ky = e / 768; int rem = e - ky * 768; int kx = rem >> 8; int ci = rem & 255;
        int iy = y + ky - 1, ix = x + kx - 1;
        if ((unsigned)iy < 128u && (unsigned)ix < 128u) {
            float f = __ldg(g_feat + ((size_t)(b * 128 + iy) * 128 + ix) * 256 + ci);
            as += f * __ldg(wsc + e);
            ay += f * __ldg(wrg + 2 * e);
            ax += f * __ldg(wrg + 2 * e + 1);
        }
    }
#pragma unroll
    for (int o = 16; o > 0; o >>= 1) {
        as += __shfl_down_sync(~0u, as, o);
        ay += __shfl_down_sync(~0u, ay, o);
        ax += __shfl_down_sync(~0u, ax, o);
    }
    if (lane == 0) {
        g_scores[b * 16384 + p] = sigmoidf(as + __ldg(bsc));
        g_reg[(b * 16384 + p) * 2]     = ay + __ldg(brg);
        g_reg[(b * 16384 + p) * 2 + 1] = ax + __ldg(brg + 1);
    }
}

// ---------------- fused seg (1x1 256->256 relu) + segr (1x1 256->32 relu) ----------------
__global__ void segseg_kernel(const float* __restrict__ wseg, const float* __restrict__ bseg,
                              const float* __restrict__ wr, const float* __restrict__ br) {
    __shared__ float sf[8 * 256];
    __shared__ float st[8 * 256];
    int b = blockIdx.y; int p0 = blockIdx.x * 8; int t = threadIdx.x;
    for (int e = t; e < 2048; e += 256)
        sf[e] = g_feat[((size_t)b * 16384 + p0) * 256 + e];   // 8 consecutive pixels are contiguous
    __syncthreads();
    {   // stage1: tmp channel c = threadIdx.x for 8 pixels
        int c = t;
        float acc[8];
#pragma unroll
        for (int p = 0; p < 8; p++) acc[p] = 0.f;
        for (int ci = 0; ci < 256; ci++) {
            float w = __ldg(wseg + ci * 256 + c);
#pragma unroll
            for (int p = 0; p < 8; p++) acc[p] += sf[p * 256 + ci] * w;
        }
        float bs = __ldg(bseg + c);
#pragma unroll
        for (int p = 0; p < 8; p++) st[p * 256 + c] = fmaxf(acc[p] + bs, 0.f);
    }
    __syncthreads();
    {   // stage2: 32 out channels x 8 pixels
        int co = t & 31, p = t >> 5;
        float a2 = 0.f;
        for (int ci = 0; ci < 256; ci++) a2 += st[p * 256 + ci] * __ldg(wr + ci * 32 + co);
        g_segr[((size_t)b * 16384 + p0 + p) * 32 + co] = fmaxf(a2 + __ldg(br + co), 0.f);
    }
}

// ---------------- top-K_PRE: full bitonic sort of 16384 packed keys per batch ----------------
// key = (float_bits(score) << 32) | (16383 - idx): descending sort => desc score, asc idx ties.
__global__ void topk_kernel() {
    extern __shared__ unsigned long long sk[];
    int b = blockIdx.x, t = threadIdx.x;
    for (int e = t; e < 16384; e += 1024) {
        unsigned fb = __float_as_uint(g_scores[b * 16384 + e]);
        sk[e] = ((unsigned long long)fb << 32) | (unsigned)(16383 - e);
    }
    for (unsigned k = 2; k <= 16384u; k <<= 1)
        for (unsigned j = k >> 1; j > 0; j >>= 1) {
            __syncthreads();
            for (unsigned e = t; e < 16384; e += 1024) {
                unsigned l = e ^ j;
                if (l > e) {
                    unsigned long long A = sk[e], C = sk[l];
                    bool desc = ((e & k) == 0);
                    if ((A < C) == desc) { sk[e] = C; sk[l] = A; }
                }
            }
        }
    __syncthreads();
    for (int e = t; e < KPRE; e += 1024) {
        unsigned long long key = sk[e];
        float s = __uint_as_float((unsigned)(key >> 32));
        int idx = 16383 - (int)(unsigned)(key & 0xFFFFFFFFu);
        g_topsc[b * KPRE + e] = s;
        float yy = (float)(idx >> 7), xx = (float)(idx & 127);
        g_locs[(b * KPRE + e) * 2]     = yy + 0.5f + g_reg[(b * 16384 + idx) * 2];
        g_locs[(b * KPRE + e) * 2 + 1] = xx + 0.5f + g_reg[(b * 16384 + idx) * 2 + 1];
    }
}

// ---------------- suppression bitmatrix: sup[i] bit j <=> dist(i,j) <= 1.1 ----------------
__global__ void sup_kernel() {
    int i = blockIdx.x, b = blockIdx.y, w = threadIdx.x;   // 64 threads
    float ly = g_locs[(b * KPRE + i) * 2], lx = g_locs[(b * KPRE + i) * 2 + 1];
    unsigned bits = 0;
    if (w < 63) {
        int j0 = w * 32;
#pragma unroll 4
        for (int u = 0; u < 32; u++) {
            int j = j0 + u;
            if (j < KPRE) {
                float dy = ly - g_locs[(b * KPRE + j) * 2];
                float dx = lx - g_locs[(b * KPRE + j) * 2 + 1];
                if (sqrtf(dy * dy + dx * dx) <= 1.1f) bits |= (1u << u);
            }
        }
    }
    g_sup[((size_t)(b * KPRE) + i) * 64 + w] = bits;
}

// ---------------- sequential greedy NMS scan (single warp/batch, deep prefetch) ----------------
__global__ void nms_scan_kernel() {
    int b = blockIdx.x, lane = threadIdx.x;   // 32 threads
    __shared__ unsigned ssup[64];
    __shared__ int slist[KOUT];
    ssup[lane] = 0; ssup[lane + 32] = 0;
    __syncwarp();
    const unsigned* base = g_sup + (size_t)b * KPRE * 64;
    unsigned ca[8], cb[8], na[8], nb[8];
#pragma unroll
    for (int u = 0; u < 8; u++) {
        ca[u] = base[(size_t)u * 64 + lane];
        cb[u] = (lane < 31) ? base[(size_t)u * 64 + 32 + lane] : 0u;
    }
    int cnt = 0;
    for (int ch = 0; ch < KPRE; ch += 8) {
        if (ch + 8 < KPRE) {
#pragma unroll
            for (int u = 0; u < 8; u++) {
                int i = ch + 8 + u;
                na[u] = base[(size_t)i * 64 + lane];
                nb[u] = (lane < 31) ? base[(size_t)i * 64 + 32 + lane] : 0u;
            }
        }
#pragma unroll
        for (int u = 0; u < 8; u++) {
            int i = ch + u;
            bool kp = ((ssup[i >> 5] >> (i & 31)) & 1u) == 0u;
            if (kp) {
                ssup[lane] |= ca[u];
                if (lane < 31) ssup[32 + lane] |= cb[u];
                if (lane == 0) { if (cnt < KOUT) slist[cnt] = i; cnt++; }
            }
            __syncwarp();
        }
#pragma unroll
        for (int u = 0; u < 8; u++) { ca[u] = na[u]; cb[u] = nb[u]; }
    }
    cnt = __shfl_sync(~0u, cnt, 0);
    if (lane == 0) g_nsel[b] = cnt;
    __syncwarp();
    int n = cnt < KOUT ? cnt : KOUT;
    for (int k = lane; k < n; k += 32) g_sel[b * KOUT + k] = slist[k];
}

// ---------------- selection: sel_s, pix outputs + crop top-lefts ----------------
__global__ void select_kernel(float* __restrict__ out) {
    int b = blockIdx.x; int k = threadIdx.x;
    if (k >= KOUT) return;
    int n = g_nsel[b]; if (n > KOUT) n = KOUT;
    bool valid = (k < n);
    float s = -1.f, ly = 0.f, lx = 0.f;
    if (valid) {
        int i = g_sel[b * KOUT + k];
        s  = g_topsc[b * KPRE + i];
        ly = g_locs[(b * KPRE + i) * 2];
        lx = g_locs[(b * KPRE + i) * 2 + 1];
    }
    float cy, cx;
    int o = b * KOUT + k;
    if (valid) {
        out[o] = s;
        out[2000 + o * 2]     = ly * 4.f;
        out[2000 + o * 2 + 1] = lx * 4.f;
        cy = ly; cx = lx;
    } else {
        out[o] = -1.f;
        out[2000 + o * 2] = -1.f;
        out[2000 + o * 2 + 1] = -1.f;
        cy = -0.25f; cx = -0.25f;    // pix=-1 -> (-1/512)*128
    }
    int ty = (int)rintf(cy) - 16; ty = min(max(ty, 0), 96);
    int tx = (int)rintf(cx) - 16; tx = min(max(tx, 0), 96);
    g_tl[o * 2] = ty; g_tl[o * 2 + 1] = tx;
}

// ---------------- inst_full: global 3x3 conv(32->32)+relu, 1x1(32->1)+sigmoid over segr ----------------
__global__ void instfull_kernel(const float* __restrict__ wp1, const float* __restrict__ bp1v,
                                const float* __restrict__ wp2, const float* __restrict__ bp2v) {
    __shared__ float sw[9216];
    __shared__ float sb1[32], sw2[32];
    int t = threadIdx.x;
    for (int e = t; e < 9216; e += 256) sw[e] = wp1[e];
    if (t < 32) { sb1[t] = bp1v[t]; sw2[t] = wp2[t]; }
    __syncthreads();
    int b = blockIdx.y;
    int warp = t >> 5, lane = t & 31;
    int p = blockIdx.x * 8 + warp;
    int y = p >> 7, x = p & 127;
    float acc = 0.f;
#pragma unroll
    for (int dy = -1; dy <= 1; dy++) {
        int iy = y + dy; if ((unsigned)iy >= 128u) continue;
#pragma unroll
        for (int dx = -1; dx <= 1; dx++) {
            int ix = x + dx; if ((unsigned)ix >= 128u) continue;
            const float* sp = g_segr + ((size_t)(b * 128 + iy) * 128 + ix) * 32;
            const float* wb = sw + ((dy + 1) * 3 + (dx + 1)) * 1024;
#pragma unroll
            for (int ci = 0; ci < 32; ci++) acc += __ldg(sp + ci) * wb[ci * 32 + lane];
        }
    }
    float h = fmaxf(acc + sb1[lane], 0.f);
    float v = h * sw2[lane];
#pragma unroll
    for (int o = 16; o > 0; o >>= 1) v += __shfl_down_sync(~0u, v, o);
    if (lane == 0) g_instfull[(size_t)(b * 128 + y) * 128 + x] = sigmoidf(v + __ldg(bp2v));
}

// ---------------- per-patch: gather interior from inst_full, recompute 124 border pixels ----------------
__global__ void patch_kernel(const float* __restrict__ wp1, const float* __restrict__ bp1v,
                             const float* __restrict__ wp2, const float* __restrict__ bp2v,
                             float* __restrict__ out) {
    __shared__ float sw[9216];
    __shared__ float sb1[32], sw2[32];
    int blk = blockIdx.x; int b = blk / KOUT, k = blk % KOUT;
    int t = threadIdx.x;
    for (int e = t; e < 9216; e += 256) sw[e] = wp1[e];
    if (t < 32) { sb1[t] = bp1v[t]; sw2[t] = wp2[t]; }
    int ty = g_tl[(b * KOUT + k) * 2], tx = g_tl[(b * KOUT + k) * 2 + 1];
    float* obase = out + 6000 + ((size_t)(b * KOUT + k)) * 1024;
    for (int e = t; e < 1024; e += 256) {
        int py = e >> 5, px = e & 31;
        if (py >= 1 && py <= 30 && px >= 1 && px <= 30)
            obase[e] = g_instfull[(size_t)(b * 128 + ty + py) * 128 + tx + px];
    }
    __syncthreads();
    float bp2s = __ldg(bp2v);
    int warp = t >> 5, lane = t & 31;
    for (int bp = warp; bp < 124; bp += 8) {
        int py, px;
        if (bp < 32)      { py = 0;       px = bp; }
        else if (bp < 64) { py = 31;      px = bp - 32; }
        else if (bp < 94) { py = bp - 63; px = 0; }
        else              { py = bp - 93; px = 31; }
        float acc = 0.f;
#pragma unroll
        for (int dy = -1; dy <= 1; dy++) {
            int ly = py + dy; if ((unsigned)ly >= 32u) continue;
#pragma unroll
            for (int dx = -1; dx <= 1; dx++) {
                int lx = px + dx; if ((unsigned)lx >= 32u) continue;
                const float* sp = g_segr + ((size_t)(b * 128 + ty + ly) * 128 + tx + lx) * 32;
                const float* wb = sw + ((dy + 1) * 3 + (dx + 1)) * 1024;
#pragma unroll
                for (int ci = 0; ci < 32; ci++) acc += __ldg(sp + ci) * wb[ci * 32 + lane];
            }
        }
        float h = fmaxf(acc + sb1[lane], 0.f);
        float v = h * sw2[lane];
#pragma unroll
        for (int o = 16; o > 0; o >>= 1) v += __shfl_down_sync(~0u, v, o);
        if (lane == 0) obase[py * 32 + px] = sigmoidf(v + bp2s);
    }
}

// ---------------- launch ----------------
extern "C" void kernel_launch(void* const* d_in, const int* in_sizes, int n_in,
                              void* d_out, int out_size) {
    const float* image = (const float*)d_in[0];
    const float* w1   = (const float*)d_in[1];
    const float* b1   = (const float*)d_in[2];
    const float* w2   = (const float*)d_in[3];
    const float* b2   = (const float*)d_in[4];
    const float* wseg = (const float*)d_in[5];
    const float* bseg = (const float*)d_in[6];
    const float* wsc  = (const float*)d_in[7];
    const float* bsc  = (const float*)d_in[8];
    const float* wrg  = (const float*)d_in[9];
    const float* brg  = (const float*)d_in[10];
    const float* wr   = (const float*)d_in[11];
    const float* br   = (const float*)d_in[12];
    const float* wp1  = (const float*)d_in[13];
    const float* bp1  = (const float*)d_in[14];
    const float* wp2  = (const float*)d_in[15];
    const float* bp2  = (const float*)d_in[16];
    float* out = (float*)d_out;

    cudaFuncSetAttribute(topk_kernel, cudaFuncAttributeMaxDynamicSharedMemorySize, 131072);

    conv1_kernel<<<dim3(64, 256, 4), dim3(64, 4)>>>(image, w1, b1);
    conv2_kernel<<<dim3(16, 32, 4), 256>>>(w2, b2);
    heads_kernel<<<dim3(2048, 4), 256>>>(wsc, bsc, wrg, brg);
    segseg_kernel<<<dim3(2048, 4), 256>>>(wseg, bseg, wr, br);
    topk_kernel<<<4, 1024, 131072>>>();
    sup_kernel<<<dim3(KPRE, 4), 64>>>();
    nms_scan_kernel<<<4, 32>>>();
    select_kernel<<<4, 512>>>(out);
    instfull_kernel<<<dim3(2048, 4), 256>>>(wp1, bp1, wp2, bp2);
    patch_kernel<<<BB * KOUT, 256>>>(wp1, bp1, wp2, bp2, out);
}

// round 2
// speedup vs baseline: 1.0017x; 1.0017x over previous
#include <cuda_runtime.h>
#include <math.h>

// ---------------- constants ----------------
#define BB 4
#define HFD 128
#define WFD 128
#define KPRE 2000
#define KOUT 500

// ---------------- scratch (device globals; no allocation allowed) ----------------
__device__ __align__(16) float g_x1[(size_t)4 * 256 * 256 * 64];       // conv1 out
__device__ __align__(16) float g_feat[(size_t)4 * 128 * 128 * 256];    // conv2 out
__device__ __align__(16) float g_segr[(size_t)4 * 128 * 128 * 32];     // reduced seg feats
__device__ __align__(16) float g_scores[4 * 16384];
__device__ __align__(16) float g_reg[4 * 16384 * 2];
__device__ __align__(16) float g_topsc[4 * KPRE];
__device__ __align__(16) float g_locs[4 * KPRE * 2];
__device__ __align__(16) unsigned g_sup[(size_t)4 * KPRE * 64];        // suppression bitmatrix
__device__ int g_sel[4 * KOUT];
__device__ int g_nsel[4];
__device__ int g_tl[4 * KOUT * 2];
__device__ __align__(16) float g_instfull[4 * 128 * 128];

__device__ __forceinline__ float sigmoidf(float z) { return 1.f / (1.f + expf(-z)); }

// ---------------- conv1: 3x3 s2, 3->64, relu. SAME => iy = 2y+ky (pad_lo=0) ----------------
__global__ void conv1_kernel(const float* __restrict__ img, const float* __restrict__ w1,
                             const float* __restrict__ b1) {
    int co = threadIdx.x;                       // 64
    int x  = blockIdx.x * 4 + threadIdx.y;      // 256
    int y  = blockIdx.y;                        // 256
    int b  = blockIdx.z;                        // 4
    float acc = 0.f;
#pragma unroll
    for (int ky = 0; ky < 3; ky++) {
        int iy = 2 * y + ky;
        if (iy >= 512) continue;
#pragma unroll
        for (int kx = 0; kx < 3; kx++) {
            int ix = 2 * x + kx;
            if (ix >= 512) continue;
            const float* ip = img + ((size_t)(b * 512 + iy) * 512 + ix) * 3;
#pragma unroll
            for (int ci = 0; ci < 3; ci++)
                acc += __ldg(ip + ci) * __ldg(w1 + ((ky * 3 + kx) * 3 + ci) * 64 + co);
        }
    }
    acc += __ldg(b1 + co);
    g_x1[((size_t)(b * 256 + y) * 256 + x) * 64 + co] = fmaxf(acc, 0.f);
}

// ---------------- conv2: 3x3 s2, 64->256, relu ----------------
// block = 256 threads = 64 co-quads x 4 output rows; 8 output cols per thread.
__global__ void conv2_kernel(const float* __restrict__ w2, const float* __restrict__ b2) {
    __shared__ float sm[9 * 17 * 64];           // input tile (rows 2y0..2y0+8, cols 2x0..2x0+16)
    int x0 = blockIdx.x * 8, y0 = blockIdx.y * 4, b = blockIdx.z;
    int t = threadIdx.x;
    for (int e = t; e < 9 * 17 * 64; e += 256) {
        int ci = e & 63; int rc = e >> 6; int c = rc % 17; int r = rc / 17;
        int iy = 2 * y0 + r, ix = 2 * x0 + c;
        float v = 0.f;
        if (iy < 256 && ix < 256) v = g_x1[((size_t)(b * 256 + iy) * 256 + ix) * 64 + ci];
        sm[e] = v;
    }
    __syncthreads();
    int co4 = t & 63, ry = t >> 6;
    float a0[8], a1[8], a2[8], a3[8];
#pragma unroll
    for (int p = 0; p < 8; p++) { a0[p] = a1[p] = a2[p] = a3[p] = 0.f; }
#pragma unroll
    for (int ky = 0; ky < 3; ky++) {
        int r = 2 * ry + ky;
#pragma unroll
        for (int kx = 0; kx < 3; kx++) {
            const float* sbase = sm + (r * 17 + kx) * 64;
            const float* wbase = w2 + (size_t)((ky * 3 + kx) * 64) * 256 + co4 * 4;
            for (int ci = 0; ci < 64; ci++) {
                float4 w = *(const float4*)(wbase + (size_t)ci * 256);
#pragma unroll
                for (int p = 0; p < 8; p++) {
                    float v = sbase[(2 * p) * 64 + ci];
                    a0[p] += v * w.x; a1[p] += v * w.y; a2[p] += v * w.z; a3[p] += v * w.w;
                }
            }
        }
    }
    int y = y0 + ry;
    float4 bb = *(const float4*)(b2 + co4 * 4);
#pragma unroll
    for (int p = 0; p < 8; p++) {
        float4 o;
        o.x = fmaxf(a0[p] + bb.x, 0.f); o.y = fmaxf(a1[p] + bb.y, 0.f);
        o.z = fmaxf(a2[p] + bb.z, 0.f); o.w = fmaxf(a3[p] + bb.w, 0.f);
        *(float4*)(g_feat + ((size_t)(b * 128 + y) * 128 + (x0 + p)) * 256 + co4 * 4) = o;
    }
}

// ---------------- detection heads: scores (sigmoid) + reg, both 3x3 s1 SAME (centered) ----------------
__global__ void heads_kernel(const float* __restrict__ wsc, const float* __restrict__ bsc,
                             const float* __restrict__ wrg, const float* __restrict__ brg) {
    int b = blockIdx.y;
    int warp = threadIdx.x >> 5, lane = threadIdx.x & 31;
    int p = blockIdx.x * 8 + warp;
    int y = p >> 7, x = p & 127;
    float as = 0.f, ay = 0.f, ax = 0.f;
    for (int e = lane; e < 2304; e += 32) {
        int ky = e / 768; int rem = e - ky * 768; int kx = rem >> 8; int ci = rem & 255;
        int iy = y + ky - 1, ix = x + kx - 1;
        if ((unsigned)iy < 128u && (unsigned)ix < 128u) {
            float f = __ldg(g_feat + ((size_t)(b * 128 + iy) * 128 + ix) * 256 + ci);
            as += f * __ldg(wsc + e);
            ay += f * __ldg(wrg + 2 * e);
            ax += f * __ldg(wrg + 2 * e + 1);
        }
    }
#pragma unroll
    for (int o = 16; o > 0; o >>= 1) {
        as += __shfl_down_sync(~0u, as, o);
        ay += __shfl_down_sync(~0u, ay, o);
        ax += __shfl_down_sync(~0u, ax, o);
    }
    if (lane == 0) {
        g_scores[b * 16384 + p] = sigmoidf(as + __ldg(bsc));
        g_reg[(b * 16384 + p) * 2]     = ay + __ldg(brg);
        g_reg[(b * 16384 + p) * 2 + 1] = ax + __ldg(brg + 1);
    }
}

// ---------------- fused seg (1x1 256->256 relu) + segr (1x1 256->32 relu) ----------------
__global__ void segseg_kernel(const float* __restrict__ wseg, const float* __restrict__ bseg,
                              const float* __restrict__ wr, const float* __restrict__ br) {
    __shared__ float sf[8 * 256];
    __shared__ float st[8 * 256];
    int b = blockIdx.y; int p0 = blockIdx.x * 8; int t = threadIdx.x;
    for (int e = t; e < 2048; e += 256)
        sf[e] = g_feat[((size_t)b * 16384 + p0) * 256 + e];   // 8 consecutive pixels are contiguous
    __syncthreads();
    {   // stage1: tmp channel c = threadIdx.x for 8 pixels
        int c = t;
        float acc[8];
#pragma unroll
        for (int p = 0; p < 8; p++) acc[p] = 0.f;
        for (int ci = 0; ci < 256; ci++) {
            float w = __ldg(wseg + ci * 256 + c);
#pragma unroll
            for (int p = 0; p < 8; p++) acc[p] += sf[p * 256 + ci] * w;
        }
        float bs = __ldg(bseg + c);
#pragma unroll
        for (int p = 0; p < 8; p++) st[p * 256 + c] = fmaxf(acc[p] + bs, 0.f);
    }
    __syncthreads();
    {   // stage2: 32 out channels x 8 pixels
        int co = t & 31, p = t >> 5;
        float a2 = 0.f;
        for (int ci = 0; ci < 256; ci++) a2 += st[p * 256 + ci] * __ldg(wr + ci * 32 + co);
        g_segr[((size_t)b * 16384 + p0 + p) * 32 + co] = fmaxf(a2 + __ldg(br + co), 0.f);
    }
}

// ---------------- top-K_PRE: full bitonic sort of 16384 packed keys per batch ----------------
// key = (float_bits(score) << 32) | (16383 - idx): descending sort => desc score, asc idx ties.
__global__ void topk_kernel() {
    extern __shared__ unsigned long long sk[];
    int b = blockIdx.x, t = threadIdx.x;
    for (int e = t; e < 16384; e += 1024) {
        unsigned fb = __float_as_uint(g_scores[b * 16384 + e]);
        sk[e] = ((unsigned long long)fb << 32) | (unsigned)(16383 - e);
    }
    for (unsigned k = 2; k <= 16384u; k <<= 1)
        for (unsigned j = k >> 1; j > 0; j >>= 1) {
            __syncthreads();
            for (unsigned e = t; e < 16384; e += 1024) {
                unsigned l = e ^ j;
                if (l > e) {
                    unsigned long long A = sk[e], C = sk[l];
                    bool desc = ((e & k) == 0);
                    if ((A < C) == desc) { sk[e] = C; sk[l] = A; }
                }
            }
        }
    __syncthreads();
    for (int e = t; e < KPRE; e += 1024) {
        unsigned long long key = sk[e];
        float s = __uint_as_float((unsigned)(key >> 32));
        int idx = 16383 - (int)(unsigned)(key & 0xFFFFFFFFu);
        g_topsc[b * KPRE + e] = s;
        float yy = (float)(idx >> 7), xx = (float)(idx & 127);
        g_locs[(b * KPRE + e) * 2]     = yy + 0.5f + g_reg[(b * 16384 + idx) * 2];
        g_locs[(b * KPRE + e) * 2 + 1] = xx + 0.5f + g_reg[(b * 16384 + idx) * 2 + 1];
    }
}

// ---------------- suppression bitmatrix: sup[i] bit j <=> dist(i,j) <= 1.1 ----------------
__global__ void sup_kernel() {
    int i = blockIdx.x, b = blockIdx.y, w = threadIdx.x;   // 64 threads
    float ly = g_locs[(b * KPRE + i) * 2], lx = g_locs[(b * KPRE + i) * 2 + 1];
    unsigned bits = 0;
    if (w < 63) {
        int j0 = w * 32;
#pragma unroll 4
        for (int u = 0; u < 32; u++) {
            int j = j0 + u;
            if (j < KPRE) {
                float dy = ly - g_locs[(b * KPRE + j) * 2];
                float dx = lx - g_locs[(b * KPRE + j) * 2 + 1];
                if (sqrtf(dy * dy + dx * dx) <= 1.1f) bits |= (1u << u);
            }
        }
    }
    g_sup[((size_t)(b * KPRE) + i) * 64 + w] = bits;
}

// ---------------- sequential greedy NMS scan (single warp/batch, deep prefetch) ----------------
__global__ void nms_scan_kernel() {
    int b = blockIdx.x, lane = threadIdx.x;   // 32 threads
    __shared__ unsigned ssup[64];
    __shared__ int slist[KOUT];
    ssup[lane] = 0; ssup[lane + 32] = 0;
    __syncwarp();
    const unsigned* base = g_sup + (size_t)b * KPRE * 64;
    unsigned ca[8], cb[8], na[8], nb[8];
#pragma unroll
    for (int u = 0; u < 8; u++) {
        ca[u] = base[(size_t)u * 64 + lane];
        cb[u] = (lane < 31) ? base[(size_t)u * 64 + 32 + lane] : 0u;
    }
    int cnt = 0;
    for (int ch = 0; ch < KPRE; ch += 8) {
        if (ch + 8 < KPRE) {
#pragma unroll
            for (int u = 0; u < 8; u++) {
                int i = ch + 8 + u;
                na[u] = base[(size_t)i * 64 + lane];
                nb[u] = (lane < 31) ? base[(size_t)i * 64 + 32 + lane] : 0u;
            }
        }
#pragma unroll
        for (int u = 0; u < 8; u++) {
            int i = ch + u;
            bool kp = ((ssup[i >> 5] >> (i & 31)) & 1u) == 0u;
            if (kp) {
                ssup[lane] |= ca[u];
                if (lane < 31) ssup[32 + lane] |= cb[u];
                if (lane == 0) { if (cnt < KOUT) slist[cnt] = i; cnt++; }
            }
            __syncwarp();
        }
#pragma unroll
        for (int u = 0; u < 8; u++) { ca[u] = na[u]; cb[u] = nb[u]; }
    }
    cnt = __shfl_sync(~0u, cnt, 0);
    if (lane == 0) g_nsel[b] = cnt;
    __syncwarp();
    int n = cnt < KOUT ? cnt : KOUT;
    for (int k = lane; k < n; k += 32) g_sel[b * KOUT + k] = slist[k];
}

// ---------------- selection: sel_s, pix outputs + crop top-lefts ----------------
__global__ void select_kernel(float* __restrict__ out) {
    int b = blockIdx.x; int k = threadIdx.x;
    if (k >= KOUT) return;
    int n = g_nsel[b]; if (n > KOUT) n = KOUT;
    bool valid = (k < n);
    float s = -1.f, ly = 0.f, lx = 0.f;
    if (valid) {
        int i = g_sel[b * KOUT + k];
        s  = g_topsc[b * KPRE + i];
        ly = g_locs[(b * KPRE + i) * 2];
        lx = g_locs[(b * KPRE + i) * 2 + 1];
    }
    float cy, cx;
    int o = b * KOUT + k;
    if (valid) {
        out[o] = s;
        out[2000 + o * 2]     = ly * 4.f;
        out[2000 + o * 2 + 1] = lx * 4.f;
        cy = ly; cx = lx;
    } else {
        out[o] = -1.f;
        out[2000 + o * 2] = -1.f;
        out[2000 + o * 2 + 1] = -1.f;
        cy = -0.25f; cx = -0.25f;    // pix=-1 -> (-1/512)*128
    }
    int ty = (int)rintf(cy) - 16; ty = min(max(ty, 0), 96);
    int tx = (int)rintf(cx) - 16; tx = min(max(tx, 0), 96);
    g_tl[o * 2] = ty; g_tl[o * 2 + 1] = tx;
}

// ---------------- inst_full: global 3x3 conv(32->32)+relu, 1x1(32->1)+sigmoid over segr ----------------
__global__ void instfull_kernel(const float* __restrict__ wp1, const float* __restrict__ bp1v,
                                const float* __restrict__ wp2, const float* __restrict__ bp2v) {
    __shared__ float sw[9216];
    __shared__ float sb1[32], sw2[32];
    int t = threadIdx.x;
    for (int e = t; e < 9216; e += 256) sw[e] = wp1[e];
    if (t < 32) { sb1[t] = bp1v[t]; sw2[t] = wp2[t]; }
    __syncthreads();
    int b = blockIdx.y;
    int warp = t >> 5, lane = t & 31;
    int p = blockIdx.x * 8 + warp;
    int y = p >> 7, x = p & 127;
    float acc = 0.f;
#pragma unroll
    for (int dy = -1; dy <= 1; dy++) {
        int iy = y + dy; if ((unsigned)iy >= 128u) continue;
#pragma unroll
        for (int dx = -1; dx <= 1; dx++) {
            int ix = x + dx; if ((unsigned)ix >= 128u) continue;
            const float* sp = g_segr + ((size_t)(b * 128 + iy) * 128 + ix) * 32;
            const float* wb = sw + ((dy + 1) * 3 + (dx + 1)) * 1024;
#pragma unroll
            for (int ci = 0; ci < 32; ci++) acc += __ldg(sp + ci) * wb[ci * 32 + lane];
        }
    }
    float h = fmaxf(acc + sb1[lane], 0.f);
    float v = h * sw2[lane];
#pragma unroll
    for (int o = 16; o > 0; o >>= 1) v += __shfl_down_sync(~0u, v, o);
    if (lane == 0) g_instfull[(size_t)(b * 128 + y) * 128 + x] = sigmoidf(v + __ldg(bp2v));
}

// ---------------- per-patch: gather interior from inst_full, recompute 124 border pixels ----------------
__global__ void patch_kernel(const float* __restrict__ wp1, const float* __restrict__ bp1v,
                             const float* __restrict__ wp2, const float* __restrict__ bp2v,
                             float* __restrict__ out) {
    __shared__ float sw[9216];
    __shared__ float sb1[32], sw2[32];
    int blk = blockIdx.x; int b = blk / KOUT, k = blk % KOUT;
    int t = threadIdx.x;
    for (int e = t; e < 9216; e += 256) sw[e] = wp1[e];
    if (t < 32) { sb1[t] = bp1v[t]; sw2[t] = wp2[t]; }
    int ty = g_tl[(b * KOUT + k) * 2], tx = g_tl[(b * KOUT + k) * 2 + 1];
    float* obase = out + 6000 + ((size_t)(b * KOUT + k)) * 1024;
    for (int e = t; e < 1024; e += 256) {
        int py = e >> 5, px = e & 31;
        if (py >= 1 && py <= 30 && px >= 1 && px <= 30)
            obase[e] = g_instfull[(size_t)(b * 128 + ty + py) * 128 + tx + px];
    }
    __syncthreads();
    float bp2s = __ldg(bp2v);
    int warp = t >> 5, lane = t & 31;
    for (int bp = warp; bp < 124; bp += 8) {
        int py, px;
        if (bp < 32)      { py = 0;       px = bp; }
        else if (bp < 64) { py = 31;      px = bp - 32; }
        else if (bp < 94) { py = bp - 63; px = 0; }
        else              { py = bp - 93; px = 31; }
        float acc = 0.f;
#pragma unroll
        for (int dy = -1; dy <= 1; dy++) {
            int ly = py + dy; if ((unsigned)ly >= 32u) continue;
#pragma unroll
            for (int dx = -1; dx <= 1; dx++) {
                int lx = px + dx; if ((unsigned)lx >= 32u) continue;
                const float* sp = g_segr + ((size_t)(b * 128 + ty + ly) * 128 + tx + lx) * 32;
                const float* wb = sw + ((dy + 1) * 3 + (dx + 1)) * 1024;
#pragma unroll
                for (int ci = 0; ci < 32; ci++) acc += __ldg(sp + ci) * wb[ci * 32 + lane];
            }
        }
        float h = fmaxf(acc + sb1[lane], 0.f);
        float v = h * sw2[lane];
#pragma unroll
        for (int o = 16; o > 0; o >>= 1) v += __shfl_down_sync(~0u, v, o);
        if (lane == 0) obase[py * 32 + px] = sigmoidf(v + bp2s);
    }
}

// ---------------- launch ----------------
extern "C" void kernel_launch(void* const* d_in, const int* in_sizes, int n_in,
                              void* d_out, int out_size) {
    const float* image = (const float*)d_in[0];
    const float* w1   = (const float*)d_in[1];
    const float* b1   = (const float*)d_in[2];
    const float* w2   = (const float*)d_in[3];
    const float* b2   = (const float*)d_in[4];
    const float* wseg = (const float*)d_in[5];
    const float* bseg = (const float*)d_in[6];
    const float* wsc  = (const float*)d_in[7];
    const float* bsc  = (const float*)d_in[8];
    const float* wrg  = (const float*)d_in[9];
    const float* brg  = (const float*)d_in[10];
    const float* wr   = (const float*)d_in[11];
    const float* br   = (const float*)d_in[12];
    const float* wp1  = (const float*)d_in[13];
    const float* bp1  = (const float*)d_in[14];
    const float* wp2  = (const float*)d_in[15];
    const float* bp2  = (const float*)d_in[16];
    float* out = (float*)d_out;

    cudaFuncSetAttribute(topk_kernel, cudaFuncAttributeMaxDynamicSharedMemorySize, 131072);

    conv1_kernel<<<dim3(64, 256, 4), dim3(64, 4)>>>(image, w1, b1);
    conv2_kernel<<<dim3(16, 32, 4), 256>>>(w2, b2);
    heads_kernel<<<dim3(2048, 4), 256>>>(wsc, bsc, wrg, brg);
    segseg_kernel<<<dim3(2048, 4), 256>>>(wseg, bseg, wr, br);
    topk_kernel<<<4, 1024, 131072>>>();
    sup_kernel<<<dim3(KPRE, 4), 64>>>();
    nms_scan_kernel<<<4, 32>>>();
    select_kernel<<<4, 512>>>(out);
    instfull_kernel<<<dim3(2048, 4), 256>>>(wp1, bp1, wp2, bp2);
    patch_kernel<<<BB * KOUT, 256>>>(wp1, bp1, wp2, bp2, out);
}